// round 5
// baseline (speedup 1.0000x reference)
#include <cuda_runtime.h>

// Problem dims
#define SEQ  8192
#define EMB  1024
#define MIDD 1024

// GEMM tiling
#define BM 128
#define BN 128
#define BK 16
#define PAD 4

// Scratch (allocation-free: __device__ globals)
__device__ float g_Q[SEQ * MIDD];                 // 32 MB
__device__ float g_K[SEQ * MIDD];                 // 32 MB
__device__ float g_V[SEQ * MIDD];                 // 32 MB
__device__ float g_S[(size_t)SEQ * (size_t)SEQ];  // 256 MB scores/weights

// ---------------------------------------------------------------------------
// Tiled SGEMM, C[M_,N_] = A[M_,K_] * op(B) (+ bias broadcast over rows).
//   BNT = true : B is [N_,K_] row-major (C = A * B^T)   -- QKV proj, Q*K^T
//   BNT = false: B is [K_,N_] row-major (C = A * B)     -- weights * V
// All dims are multiples of the tile sizes (no bounds checks).
// 256 threads, 8x8 outputs/thread with 4+4 split, double-buffered smem,
// register-staged global prefetch, one __syncthreads per k-tile.
// ---------------------------------------------------------------------------
template <bool BNT>
__global__ __launch_bounds__(256)
void gemm128(const float* __restrict__ A, const float* __restrict__ B,
             const float* __restrict__ bias, float* __restrict__ C,
             int M_, int N_, int K_)
{
    __shared__ float As[2][BK][BM + PAD];
    __shared__ float Bs[2][BK][BN + PAD];

    const int tid = threadIdx.x;
    const int tx  = tid & 15;   // 0..15
    const int ty  = tid >> 4;   // 0..15
    const int bm  = blockIdx.y * BM;
    const int bn  = blockIdx.x * BN;

    // Loader mapping for A (and B when BNT): rows lr, lr+64; k-quad lk4
    const int lr  = tid >> 2;         // 0..63
    const int lk4 = (tid & 3) << 2;   // 0,4,8,12

    // Loader mapping for B when !BNT: rows br, br+8; col-quad bc4
    const int br  = tid >> 5;         // 0..7
    const int bc4 = (tid & 31) << 2;  // 0..124

    const float* Ap = A + (size_t)(bm + lr) * K_ + lk4;
    const float* Bp = BNT ? (B + (size_t)(bn + lr) * K_ + lk4)
                          : (B + (size_t)br * N_ + bn + bc4);

    const int KT = K_ / BK;

    float4 ra0, ra1, rb0, rb1;
    // prefetch k-tile 0 into registers
    ra0 = *(const float4*)(Ap);
    ra1 = *(const float4*)(Ap + (size_t)64 * K_);
    if (BNT) {
        rb0 = *(const float4*)(Bp);
        rb1 = *(const float4*)(Bp + (size_t)64 * K_);
    } else {
        rb0 = *(const float4*)(Bp);
        rb1 = *(const float4*)(Bp + (size_t)8 * N_);
    }

    float acc[8][8];
#pragma unroll
    for (int i = 0; i < 8; ++i)
#pragma unroll
        for (int j = 0; j < 8; ++j) acc[i][j] = 0.0f;

    for (int kt = 0; kt < KT; ++kt) {
        const int buf = kt & 1;

        // store staged registers -> smem[buf] (A transposed to [k][m])
        As[buf][lk4 + 0][lr]      = ra0.x;
        As[buf][lk4 + 1][lr]      = ra0.y;
        As[buf][lk4 + 2][lr]      = ra0.z;
        As[buf][lk4 + 3][lr]      = ra0.w;
        As[buf][lk4 + 0][lr + 64] = ra1.x;
        As[buf][lk4 + 1][lr + 64] = ra1.y;
        As[buf][lk4 + 2][lr + 64] = ra1.z;
        As[buf][lk4 + 3][lr + 64] = ra1.w;
        if (BNT) {
            Bs[buf][lk4 + 0][lr]      = rb0.x;
            Bs[buf][lk4 + 1][lr]      = rb0.y;
            Bs[buf][lk4 + 2][lr]      = rb0.z;
            Bs[buf][lk4 + 3][lr]      = rb0.w;
            Bs[buf][lk4 + 0][lr + 64] = rb1.x;
            Bs[buf][lk4 + 1][lr + 64] = rb1.y;
            Bs[buf][lk4 + 2][lr + 64] = rb1.z;
            Bs[buf][lk4 + 3][lr + 64] = rb1.w;
        } else {
            *(float4*)&Bs[buf][br][bc4]     = rb0;
            *(float4*)&Bs[buf][br + 8][bc4] = rb1;
        }
        __syncthreads();

        // issue next tile's global loads (overlap with compute)
        if (kt + 1 < KT) {
            const float* Ap2 = Ap + (size_t)(kt + 1) * BK;
            ra0 = *(const float4*)(Ap2);
            ra1 = *(const float4*)(Ap2 + (size_t)64 * K_);
            if (BNT) {
                const float* Bp2 = Bp + (size_t)(kt + 1) * BK;
                rb0 = *(const float4*)(Bp2);
                rb1 = *(const float4*)(Bp2 + (size_t)64 * K_);
            } else {
                const float* Bp2 = Bp + (size_t)(kt + 1) * BK * N_;
                rb0 = *(const float4*)(Bp2);
                rb1 = *(const float4*)(Bp2 + (size_t)8 * N_);
            }
        }

        // compute on smem[buf]
#pragma unroll
        for (int k = 0; k < BK; ++k) {
            float4 a0 = *(const float4*)&As[buf][k][ty * 4];
            float4 a1 = *(const float4*)&As[buf][k][64 + ty * 4];
            float4 b0 = *(const float4*)&Bs[buf][k][tx * 4];
            float4 b1 = *(const float4*)&Bs[buf][k][64 + tx * 4];
            float av[8] = {a0.x, a0.y, a0.z, a0.w, a1.x, a1.y, a1.z, a1.w};
            float bv[8] = {b0.x, b0.y, b0.z, b0.w, b1.x, b1.y, b1.z, b1.w};
#pragma unroll
            for (int i = 0; i < 8; ++i)
#pragma unroll
                for (int j = 0; j < 8; ++j)
                    acc[i][j] = fmaf(av[i], bv[j], acc[i][j]);
        }
        // double buffering: next iteration's smem stores hit the other buffer,
        // and the barrier above already ordered them vs. older reads.
    }

    // epilogue (+ optional bias)
    float bs0[4] = {0.f, 0.f, 0.f, 0.f};
    float bs1[4] = {0.f, 0.f, 0.f, 0.f};
    if (bias) {
        float4 t0 = *(const float4*)(bias + bn + tx * 4);
        float4 t1 = *(const float4*)(bias + bn + 64 + tx * 4);
        bs0[0] = t0.x; bs0[1] = t0.y; bs0[2] = t0.z; bs0[3] = t0.w;
        bs1[0] = t1.x; bs1[1] = t1.y; bs1[2] = t1.z; bs1[3] = t1.w;
    }
#pragma unroll
    for (int i = 0; i < 8; ++i) {
        const int row = bm + ((i < 4) ? (ty * 4 + i) : (64 + ty * 4 + (i - 4)));
        float* Cp = C + (size_t)row * N_ + bn;
        float4 o0 = make_float4(acc[i][0] + bs0[0], acc[i][1] + bs0[1],
                                acc[i][2] + bs0[2], acc[i][3] + bs0[3]);
        float4 o1 = make_float4(acc[i][4] + bs1[0], acc[i][5] + bs1[1],
                                acc[i][6] + bs1[2], acc[i][7] + bs1[3]);
        *(float4*)(Cp + tx * 4)      = o0;
        *(float4*)(Cp + 64 + tx * 4) = o1;
    }
}

// ---------------------------------------------------------------------------
// In-place row scaling by rsqrt(sum of squares). One block per row.
// 256 threads x float4 covers MIDD=1024 exactly.
// ---------------------------------------------------------------------------
__global__ __launch_bounds__(256)
void rnorm_scale(float* __restrict__ X)
{
    float4* p = (float4*)(X + (size_t)blockIdx.x * MIDD);
    const int t = threadIdx.x;  // 0..255
    float4 v = p[t];
    float s = v.x * v.x + v.y * v.y + v.z * v.z + v.w * v.w;
#pragma unroll
    for (int o = 16; o > 0; o >>= 1) s += __shfl_xor_sync(0xffffffffu, s, o);
    __shared__ float sh[8];
    if ((t & 31) == 0) sh[t >> 5] = s;
    __syncthreads();
    float tot = 0.f;
#pragma unroll
    for (int i = 0; i < 8; ++i) tot += sh[i];
    const float inv = rsqrtf(tot);
    v.x *= inv; v.y *= inv; v.z *= inv; v.w *= inv;
    p[t] = v;
}

// ---------------------------------------------------------------------------
// Row softmax over an 8192-wide row. One 1024-thread block per row; the whole
// row lives in registers (8 floats/thread). Scores are cosine sims in [-1,1].
// ---------------------------------------------------------------------------
__global__ __launch_bounds__(1024)
void softmax_rows(float* __restrict__ Sm)
{
    float4* p = (float4*)(Sm + (size_t)blockIdx.x * SEQ);
    const int t = threadIdx.x;  // 0..1023
    float4 v0 = p[t];
    float4 v1 = p[t + 1024];

    float m = fmaxf(fmaxf(fmaxf(v0.x, v0.y), fmaxf(v0.z, v0.w)),
                    fmaxf(fmaxf(v1.x, v1.y), fmaxf(v1.z, v1.w)));
#pragma unroll
    for (int o = 16; o > 0; o >>= 1) m = fmaxf(m, __shfl_xor_sync(0xffffffffu, m, o));
    __shared__ float sh[32];
    if ((t & 31) == 0) sh[t >> 5] = m;
    __syncthreads();
    float bmax = sh[0];
#pragma unroll
    for (int i = 1; i < 32; ++i) bmax = fmaxf(bmax, sh[i]);

    v0.x = __expf(v0.x - bmax); v0.y = __expf(v0.y - bmax);
    v0.z = __expf(v0.z - bmax); v0.w = __expf(v0.w - bmax);
    v1.x = __expf(v1.x - bmax); v1.y = __expf(v1.y - bmax);
    v1.z = __expf(v1.z - bmax); v1.w = __expf(v1.w - bmax);

    float s = v0.x + v0.y + v0.z + v0.w + v1.x + v1.y + v1.z + v1.w;
#pragma unroll
    for (int o = 16; o > 0; o >>= 1) s += __shfl_xor_sync(0xffffffffu, s, o);
    __syncthreads();  // protect sh reuse
    if ((t & 31) == 0) sh[t >> 5] = s;
    __syncthreads();
    float tot = 0.f;
#pragma unroll
    for (int i = 0; i < 32; ++i) tot += sh[i];
    const float inv = 1.0f / tot;

    v0.x *= inv; v0.y *= inv; v0.z *= inv; v0.w *= inv;
    v1.x *= inv; v1.y *= inv; v1.z *= inv; v1.w *= inv;
    p[t] = v0;
    p[t + 1024] = v1;
}

// ---------------------------------------------------------------------------
// Launch: 3x QKV proj GEMMs -> Q,K row-normalize -> Q*K^T -> softmax -> W*V
// All launches on the default stream; no allocs, no syncs (graph-capturable).
// ---------------------------------------------------------------------------
extern "C" void kernel_launch(void* const* d_in, const int* in_sizes, int n_in,
                              void* d_out, int out_size)
{
    const float* X  = (const float*)d_in[0];
    const float* Wq = (const float*)d_in[1];
    const float* bq = (const float*)d_in[2];
    const float* Wk = (const float*)d_in[3];
    const float* bk = (const float*)d_in[4];
    const float* Wv = (const float*)d_in[5];
    const float* bv = (const float*)d_in[6];
    float* out = (float*)d_out;

    float *Q, *K, *V, *Sc;
    cudaGetSymbolAddress((void**)&Q,  g_Q);
    cudaGetSymbolAddress((void**)&K,  g_K);
    cudaGetSymbolAddress((void**)&V,  g_V);
    cudaGetSymbolAddress((void**)&Sc, g_S);

    const dim3 blk(256);

    // Q/K/V = X @ W^T + b   (NT: W is [MID, EMB] row-major)
    const dim3 gQKV(MIDD / BN, SEQ / BM);
    gemm128<true><<<gQKV, blk>>>(X, Wq, bq, Q, SEQ, MIDD, EMB);
    gemm128<true><<<gQKV, blk>>>(X, Wk, bk, K, SEQ, MIDD, EMB);
    gemm128<true><<<gQKV, blk>>>(X, Wv, bv, V, SEQ, MIDD, EMB);

    // fold cosine normalization into the operands
    rnorm_scale<<<SEQ, 256>>>(Q);
    rnorm_scale<<<SEQ, 256>>>(K);

    // scores = Qn @ Kn^T  (NT), [8192 x 8192]
    const dim3 gS(SEQ / BN, SEQ / BM);
    gemm128<true><<<gS, blk>>>(Q, K, nullptr, Sc, SEQ, SEQ, MIDD);

    // row softmax in place
    softmax_rows<<<SEQ, 1024>>>(Sc);

    // out = weights @ V  (NN), [8192 x 1024]
    const dim3 gO(MIDD / BN, SEQ / BM);
    gemm128<false><<<gO, blk>>>(Sc, V, nullptr, out, SEQ, MIDD, SEQ);
}

// round 13
// speedup vs baseline: 3.1979x; 3.1979x over previous
#include <cuda_runtime.h>
#include <cuda_bf16.h>
#include <cstdint>

#define SEQ  8192
#define EMB  1024
#define MIDD 1024

// ---------------------------------------------------------------------------
// Scratch (__device__ globals: allocation-free)
// ---------------------------------------------------------------------------
__device__ float g_Q[SEQ * MIDD];
__device__ float g_K[SEQ * MIDD];
__device__ float g_V[SEQ * MIDD];
__device__ float g_S[(size_t)SEQ * (size_t)SEQ];  // fp32 scores (256 MB)

__device__ __nv_bfloat16 g_Xh[SEQ * EMB],  g_Xl[SEQ * EMB];
__device__ __nv_bfloat16 g_Wqh[MIDD * EMB], g_Wql[MIDD * EMB];
__device__ __nv_bfloat16 g_Wkh[MIDD * EMB], g_Wkl[MIDD * EMB];
__device__ __nv_bfloat16 g_Wvh[MIDD * EMB], g_Wvl[MIDD * EMB];
__device__ __nv_bfloat16 g_Qh[SEQ * MIDD], g_Ql[SEQ * MIDD];
__device__ __nv_bfloat16 g_Kh[SEQ * MIDD], g_Kl[SEQ * MIDD];
__device__ __nv_bfloat16 g_Vth[(size_t)MIDD * SEQ], g_Vtl[(size_t)MIDD * SEQ];  // V^T
__device__ __nv_bfloat16 g_Ph[(size_t)SEQ * SEQ], g_Pl[(size_t)SEQ * SEQ];      // weights

// ---------------------------------------------------------------------------
// PTX helpers — ONLY compute_103-legal instructions (no tcgen05 / no 'a'):
// cp.async (sm_80), ldmatrix (sm_75), mma.sync bf16 (sm_80).
// ---------------------------------------------------------------------------
static __device__ __forceinline__ uint32_t smem_u32(const void* p) {
    uint32_t a;
    asm("{ .reg .u64 t; cvta.to.shared.u64 t, %1; cvt.u32.u64 %0, t; }"
        : "=r"(a) : "l"(p));
    return a;
}

#define CP_ASYNC16(saddr, gptr) \
    asm volatile("cp.async.cg.shared.global [%0], [%1], 16;" \
                 :: "r"(saddr), "l"(gptr))
#define CP_COMMIT() asm volatile("cp.async.commit_group;" ::: "memory")
#define CP_WAIT0()  asm volatile("cp.async.wait_group 0;" ::: "memory")

static __device__ __forceinline__ void ldmx4(uint32_t* r, uint32_t addr) {
    asm volatile("ldmatrix.sync.aligned.m8n8.x4.shared.b16 {%0,%1,%2,%3}, [%4];"
                 : "=r"(r[0]), "=r"(r[1]), "=r"(r[2]), "=r"(r[3]) : "r"(addr));
}

static __device__ __forceinline__ void mma_bf16(float* c, const uint32_t* a,
                                                const uint32_t* b) {
    asm volatile(
        "mma.sync.aligned.m16n8k16.row.col.f32.bf16.bf16.f32 "
        "{%0,%1,%2,%3}, {%4,%5,%6,%7}, {%8,%9}, {%0,%1,%2,%3};"
        : "+f"(c[0]), "+f"(c[1]), "+f"(c[2]), "+f"(c[3])
        : "r"(a[0]), "r"(a[1]), "r"(a[2]), "r"(a[3]), "r"(b[0]), "r"(b[1]));
}

// ---------------------------------------------------------------------------
// Split-bf16 NT GEMM on HMMA: C[M_,N_] = (Ah+Al)(Bh+Bl)^T (+bias), fp32 out.
// A*: [M_,K_] bf16 row-major.  B*: [N_,K_] bf16 row-major (NT).
// Tile 128x128, BK=64 (128B rows, SW128 xor-swizzle -> conflict-free ldmatrix),
// 8 warps (4 along M x 2 along N), each warp 32x64 via m16n8k16 fragments.
// 3 MMA passes per fragment: AhBh + AhBl + AlBh (residual ~ eps_bf16^2).
// 2-stage cp.async pipeline.
// ---------------------------------------------------------------------------
#define STAGE   65536     // 4 operand quadrants x 16 KB
#define OFF_AH  0
#define OFF_AL  16384
#define OFF_BH  32768
#define OFF_BL  49152
#define GT_SMEM (2 * STAGE + 1024)

__global__ __launch_bounds__(256, 1)
void gemm_tc(const __nv_bfloat16* __restrict__ Ah, const __nv_bfloat16* __restrict__ Al,
             const __nv_bfloat16* __restrict__ Bh, const __nv_bfloat16* __restrict__ Bl,
             const float* __restrict__ bias, float* __restrict__ C,
             int M_, int N_, int K_)
{
    extern __shared__ char smem_raw[];
    const uint32_t raw = smem_u32(smem_raw);
    const uint32_t SB = (raw + 1023u) & ~1023u;  // 1KB-align buffers

    const int tid = threadIdx.x;
    const int wid = tid >> 5;
    const int lane = tid & 31;
    const int warp_m = wid & 3;   // 0..3 -> 32-row slab
    const int warp_n = wid >> 2;  // 0..1 -> 64-col slab
    const int bm = blockIdx.y * 128;
    const int bn = blockIdx.x * 128;

    // ---- per-thread loader precompute (4x 16B chunks per quadrant) ----
    int l_row[4], l_soff[4];
    size_t l_ga[4], l_gb[4];
#pragma unroll
    for (int i = 0; i < 4; ++i) {
        const int idx = tid + i * 256;   // 0..1023
        const int row = idx >> 3;        // 0..127
        const int ch  = idx & 7;         // 16B chunk in 128B row
        l_row[i]  = row;
        l_soff[i] = row * 128 + ((ch ^ (row & 7)) << 4);
        l_ga[i] = (size_t)(bm + row) * K_ + ch * 8;
        l_gb[i] = (size_t)(bn + row) * K_ + ch * 8;
    }

    auto issue = [&](int t) {
        const uint32_t buf = SB + (t & 1) * STAGE;
        const size_t kofs = (size_t)t * 64;
#pragma unroll
        for (int i = 0; i < 4; ++i) {
            CP_ASYNC16(buf + OFF_AH + l_soff[i], Ah + l_ga[i] + kofs);
            CP_ASYNC16(buf + OFF_AL + l_soff[i], Al + l_ga[i] + kofs);
            CP_ASYNC16(buf + OFF_BH + l_soff[i], Bh + l_gb[i] + kofs);
            CP_ASYNC16(buf + OFF_BL + l_soff[i], Bl + l_gb[i] + kofs);
        }
        CP_COMMIT();
    };

    // ---- ldmatrix address components ----
    // A x4: lanes 0-7: m0-7@k0 | 8-15: m8-15@k0 | 16-23: m0-7@k8 | 24-31: m8-15@k8
    const int a_rit = (lane & 7) + ((lane >> 3) & 1) * 8;  // row in 16-tile
    const int a_kq  = lane >> 4;                           // +1 chunk (k+8)
    // B x4: lanes 0-7: n0-7@k0 | 8-15: n0-7@k8 | 16-23: n8-15@k0 | 24-31: n8-15@k8
    const int b_rit = (lane & 7) + (lane >> 4) * 8;
    const int b_kq  = (lane >> 3) & 1;

    float acc[2][8][4];
#pragma unroll
    for (int mt = 0; mt < 2; ++mt)
#pragma unroll
        for (int n8 = 0; n8 < 8; ++n8)
#pragma unroll
            for (int j = 0; j < 4; ++j) acc[mt][n8][j] = 0.f;

    const int KT = K_ / 64;
    issue(0);

#pragma unroll 1
    for (int t = 0; t < KT; ++t) {
        CP_WAIT0();
        __syncthreads();
        if (t + 1 < KT) issue(t + 1);

        const uint32_t buf = SB + (t & 1) * STAGE;
#pragma unroll
        for (int s = 0; s < 4; ++s) {
            uint32_t ah[2][4], al[2][4], bh[4][4], bl[4][4];
            // A fragments (2 m16 tiles, hi+lo)
#pragma unroll
            for (int mt = 0; mt < 2; ++mt) {
                const int row = warp_m * 32 + mt * 16 + a_rit;
                const int ck  = s * 2 + a_kq;
                const uint32_t off = row * 128 + ((ck ^ (row & 7)) << 4);
                ldmx4(ah[mt], buf + OFF_AH + off);
                ldmx4(al[mt], buf + OFF_AL + off);
            }
            // B fragments (4 x4-loads covering 8 n8 tiles, hi+lo)
#pragma unroll
            for (int nt = 0; nt < 4; ++nt) {
                const int row = warp_n * 64 + nt * 16 + b_rit;
                const int ck  = s * 2 + b_kq;
                const uint32_t off = row * 128 + ((ck ^ (row & 7)) << 4);
                ldmx4(bh[nt], buf + OFF_BH + off);
                ldmx4(bl[nt], buf + OFF_BL + off);
            }
            // 3 passes: AhBh + AhBl + AlBh
#pragma unroll
            for (int mt = 0; mt < 2; ++mt)
#pragma unroll
                for (int n8 = 0; n8 < 8; ++n8) {
                    const uint32_t* ph = &bh[n8 >> 1][(n8 & 1) * 2];
                    const uint32_t* pl = &bl[n8 >> 1][(n8 & 1) * 2];
                    mma_bf16(acc[mt][n8], ah[mt], ph);
                    mma_bf16(acc[mt][n8], ah[mt], pl);
                    mma_bf16(acc[mt][n8], al[mt], ph);
                }
        }
        __syncthreads();  // all warps done reading buf before it is refilled
    }

    // ---- epilogue: c-fragment -> gmem (coalesced float2), + bias ----
    const int g  = lane >> 2;   // fragment row 0..7
    const int tg = lane & 3;    // col pair 0..3
#pragma unroll
    for (int mt = 0; mt < 2; ++mt) {
        const int row0 = bm + warp_m * 32 + mt * 16 + g;
#pragma unroll
        for (int n8 = 0; n8 < 8; ++n8) {
            const int col = bn + warp_n * 64 + n8 * 8 + tg * 2;
            float2 b2 = make_float2(0.f, 0.f);
            if (bias) b2 = *(const float2*)(bias + col);
            float2 v0 = make_float2(acc[mt][n8][0] + b2.x, acc[mt][n8][1] + b2.y);
            float2 v1 = make_float2(acc[mt][n8][2] + b2.x, acc[mt][n8][3] + b2.y);
            *(float2*)(C + (size_t)row0 * N_ + col)       = v0;
            *(float2*)(C + (size_t)(row0 + 8) * N_ + col) = v1;
        }
    }
}

// ---------------------------------------------------------------------------
// fp32 -> (hi, lo) bf16 split
// ---------------------------------------------------------------------------
static __device__ __forceinline__ void split1(float x, __nv_bfloat16& h, __nv_bfloat16& l) {
    h = __float2bfloat16(x);
    l = __float2bfloat16(x - __bfloat162float(h));
}

__global__ __launch_bounds__(256)
void split_hilo(const float* __restrict__ x, __nv_bfloat16* __restrict__ H,
                __nv_bfloat16* __restrict__ L, int n4)
{
    int i = blockIdx.x * 256 + threadIdx.x;
    if (i >= n4) return;
    float4 v = ((const float4*)x)[i];
    __nv_bfloat16 h0, h1, h2, h3, l0, l1, l2, l3;
    split1(v.x, h0, l0); split1(v.y, h1, l1);
    split1(v.z, h2, l2); split1(v.w, h3, l3);
    ((__nv_bfloat162*)H)[2 * i]     = __halves2bfloat162(h0, h1);
    ((__nv_bfloat162*)H)[2 * i + 1] = __halves2bfloat162(h2, h3);
    ((__nv_bfloat162*)L)[2 * i]     = __halves2bfloat162(l0, l1);
    ((__nv_bfloat162*)L)[2 * i + 1] = __halves2bfloat162(l2, l3);
}

// ---------------------------------------------------------------------------
// Row rsqrt-norm + split to bf16 hi/lo. One block per row (MIDD=1024).
// ---------------------------------------------------------------------------
__global__ __launch_bounds__(256)
void rnorm_hilo(const float* __restrict__ X, __nv_bfloat16* __restrict__ H,
                __nv_bfloat16* __restrict__ L)
{
    const size_t roff = (size_t)blockIdx.x * MIDD;
    const float4* p = (const float4*)(X + roff);
    const int t = threadIdx.x;
    float4 v = p[t];
    float s = v.x * v.x + v.y * v.y + v.z * v.z + v.w * v.w;
#pragma unroll
    for (int o = 16; o > 0; o >>= 1) s += __shfl_xor_sync(0xffffffffu, s, o);
    __shared__ float sh[8];
    if ((t & 31) == 0) sh[t >> 5] = s;
    __syncthreads();
    float tot = 0.f;
#pragma unroll
    for (int i = 0; i < 8; ++i) tot += sh[i];
    const float inv = rsqrtf(tot);
    v.x *= inv; v.y *= inv; v.z *= inv; v.w *= inv;
    __nv_bfloat16 h0, h1, h2, h3, l0, l1, l2, l3;
    split1(v.x, h0, l0); split1(v.y, h1, l1);
    split1(v.z, h2, l2); split1(v.w, h3, l3);
    __nv_bfloat162* H2 = (__nv_bfloat162*)(H + roff);
    __nv_bfloat162* L2 = (__nv_bfloat162*)(L + roff);
    H2[2 * t]     = __halves2bfloat162(h0, h1);
    H2[2 * t + 1] = __halves2bfloat162(h2, h3);
    L2[2 * t]     = __halves2bfloat162(l0, l1);
    L2[2 * t + 1] = __halves2bfloat162(l2, l3);
}

// ---------------------------------------------------------------------------
// V [SEQ, MIDD] fp32 -> V^T hi/lo bf16 [MIDD, SEQ]
// ---------------------------------------------------------------------------
__global__ __launch_bounds__(256)
void transpose_hilo(const float* __restrict__ V, __nv_bfloat16* __restrict__ Th,
                    __nv_bfloat16* __restrict__ Tl)
{
    __shared__ float tile[32][33];
    const int tx = threadIdx.x;
    const int ty = threadIdx.y;
    const int x0 = blockIdx.x * 32;
    const int y0 = blockIdx.y * 32;
#pragma unroll
    for (int j = ty; j < 32; j += 8)
        tile[j][tx] = V[(size_t)(y0 + j) * MIDD + x0 + tx];
    __syncthreads();
#pragma unroll
    for (int j = ty; j < 32; j += 8) {
        float val = tile[tx][j];
        __nv_bfloat16 h, l;
        split1(val, h, l);
        const size_t o = (size_t)(x0 + j) * SEQ + y0 + tx;
        Th[o] = h;
        Tl[o] = l;
    }
}

// ---------------------------------------------------------------------------
// Row softmax over fp32 scores, emits hi/lo bf16 weights. 1024 thr/row.
// ---------------------------------------------------------------------------
__global__ __launch_bounds__(1024)
void softmax_hilo(const float* __restrict__ Sm, __nv_bfloat16* __restrict__ H,
                  __nv_bfloat16* __restrict__ L)
{
    const size_t roff = (size_t)blockIdx.x * SEQ;
    const float4* p = (const float4*)(Sm + roff);
    const int t = threadIdx.x;
    float4 v0 = p[t];
    float4 v1 = p[t + 1024];

    float m = fmaxf(fmaxf(fmaxf(v0.x, v0.y), fmaxf(v0.z, v0.w)),
                    fmaxf(fmaxf(v1.x, v1.y), fmaxf(v1.z, v1.w)));
#pragma unroll
    for (int o = 16; o > 0; o >>= 1) m = fmaxf(m, __shfl_xor_sync(0xffffffffu, m, o));
    __shared__ float sh[32];
    if ((t & 31) == 0) sh[t >> 5] = m;
    __syncthreads();
    float bmax = sh[0];
#pragma unroll
    for (int i = 1; i < 32; ++i) bmax = fmaxf(bmax, sh[i]);

    v0.x = __expf(v0.x - bmax); v0.y = __expf(v0.y - bmax);
    v0.z = __expf(v0.z - bmax); v0.w = __expf(v0.w - bmax);
    v1.x = __expf(v1.x - bmax); v1.y = __expf(v1.y - bmax);
    v1.z = __expf(v1.z - bmax); v1.w = __expf(v1.w - bmax);

    float s = v0.x + v0.y + v0.z + v0.w + v1.x + v1.y + v1.z + v1.w;
#pragma unroll
    for (int o = 16; o > 0; o >>= 1) s += __shfl_xor_sync(0xffffffffu, s, o);
    __syncthreads();
    if ((t & 31) == 0) sh[t >> 5] = s;
    __syncthreads();
    float tot = 0.f;
#pragma unroll
    for (int i = 0; i < 32; ++i) tot += sh[i];
    const float inv = 1.0f / tot;

    v0.x *= inv; v0.y *= inv; v0.z *= inv; v0.w *= inv;
    v1.x *= inv; v1.y *= inv; v1.z *= inv; v1.w *= inv;

    __nv_bfloat162* H2 = (__nv_bfloat162*)(H + roff);
    __nv_bfloat162* L2 = (__nv_bfloat162*)(L + roff);
    __nv_bfloat16 h0, h1, h2, h3, l0, l1, l2, l3;
    split1(v0.x, h0, l0); split1(v0.y, h1, l1);
    split1(v0.z, h2, l2); split1(v0.w, h3, l3);
    H2[2 * t]     = __halves2bfloat162(h0, h1);
    H2[2 * t + 1] = __halves2bfloat162(h2, h3);
    L2[2 * t]     = __halves2bfloat162(l0, l1);
    L2[2 * t + 1] = __halves2bfloat162(l2, l3);
    split1(v1.x, h0, l0); split1(v1.y, h1, l1);
    split1(v1.z, h2, l2); split1(v1.w, h3, l3);
    H2[2048 + 2 * t]     = __halves2bfloat162(h0, h1);
    H2[2048 + 2 * t + 1] = __halves2bfloat162(h2, h3);
    L2[2048 + 2 * t]     = __halves2bfloat162(l0, l1);
    L2[2048 + 2 * t + 1] = __halves2bfloat162(l2, l3);
}

// ---------------------------------------------------------------------------
// Orchestration (graph-capturable: launches only)
// ---------------------------------------------------------------------------
extern "C" void kernel_launch(void* const* d_in, const int* in_sizes, int n_in,
                              void* d_out, int out_size)
{
    const float* X  = (const float*)d_in[0];
    const float* Wq = (const float*)d_in[1];
    const float* bq = (const float*)d_in[2];
    const float* Wk = (const float*)d_in[3];
    const float* bk = (const float*)d_in[4];
    const float* Wv = (const float*)d_in[5];
    const float* bv = (const float*)d_in[6];
    float* out = (float*)d_out;

    float *Qf, *Kf, *Vf, *Sc;
    __nv_bfloat16 *Xh, *Xl, *Wqh, *Wql, *Wkh, *Wkl, *Wvh, *Wvl;
    __nv_bfloat16 *Qh, *Ql, *Kh, *Kl, *Vth, *Vtl, *Ph, *Pl;
    cudaGetSymbolAddress((void**)&Qf, g_Q);
    cudaGetSymbolAddress((void**)&Kf, g_K);
    cudaGetSymbolAddress((void**)&Vf, g_V);
    cudaGetSymbolAddress((void**)&Sc, g_S);
    cudaGetSymbolAddress((void**)&Xh, g_Xh);   cudaGetSymbolAddress((void**)&Xl, g_Xl);
    cudaGetSymbolAddress((void**)&Wqh, g_Wqh); cudaGetSymbolAddress((void**)&Wql, g_Wql);
    cudaGetSymbolAddress((void**)&Wkh, g_Wkh); cudaGetSymbolAddress((void**)&Wkl, g_Wkl);
    cudaGetSymbolAddress((void**)&Wvh, g_Wvh); cudaGetSymbolAddress((void**)&Wvl, g_Wvl);
    cudaGetSymbolAddress((void**)&Qh, g_Qh);   cudaGetSymbolAddress((void**)&Ql, g_Ql);
    cudaGetSymbolAddress((void**)&Kh, g_Kh);   cudaGetSymbolAddress((void**)&Kl, g_Kl);
    cudaGetSymbolAddress((void**)&Vth, g_Vth); cudaGetSymbolAddress((void**)&Vtl, g_Vtl);
    cudaGetSymbolAddress((void**)&Ph, g_Ph);   cudaGetSymbolAddress((void**)&Pl, g_Pl);

    cudaFuncSetAttribute(gemm_tc, cudaFuncAttributeMaxDynamicSharedMemorySize, GT_SMEM);

    // split inputs to bf16 hi/lo
    split_hilo<<<SEQ * EMB / 4 / 256, 256>>>(X, Xh, Xl, SEQ * EMB / 4);
    split_hilo<<<MIDD * EMB / 4 / 256, 256>>>(Wq, Wqh, Wql, MIDD * EMB / 4);
    split_hilo<<<MIDD * EMB / 4 / 256, 256>>>(Wk, Wkh, Wkl, MIDD * EMB / 4);
    split_hilo<<<MIDD * EMB / 4 / 256, 256>>>(Wv, Wvh, Wvl, MIDD * EMB / 4);

    // Q/K/V = X @ W^T + b
    dim3 gQKV(MIDD / 128, SEQ / 128);
    gemm_tc<<<gQKV, 256, GT_SMEM>>>(Xh, Xl, Wqh, Wql, bq, Qf, SEQ, MIDD, EMB);
    gemm_tc<<<gQKV, 256, GT_SMEM>>>(Xh, Xl, Wkh, Wkl, bk, Kf, SEQ, MIDD, EMB);
    gemm_tc<<<gQKV, 256, GT_SMEM>>>(Xh, Xl, Wvh, Wvl, bv, Vf, SEQ, MIDD, EMB);

    // cosine norms folded into operands; V transposed for NT form
    rnorm_hilo<<<SEQ, 256>>>(Qf, Qh, Ql);
    rnorm_hilo<<<SEQ, 256>>>(Kf, Kh, Kl);
    transpose_hilo<<<dim3(MIDD / 32, SEQ / 32), dim3(32, 8)>>>(Vf, Vth, Vtl);

    // scores = Qn @ Kn^T
    gemm_tc<<<dim3(SEQ / 128, SEQ / 128), 256, GT_SMEM>>>(
        Qh, Ql, Kh, Kl, nullptr, Sc, SEQ, SEQ, MIDD);

    // softmax -> bf16 hi/lo weights
    softmax_hilo<<<SEQ, 1024>>>(Sc, Ph, Pl);

    // out = weights @ V = weights @ (V^T)^T
    gemm_tc<<<dim3(MIDD / 128, SEQ / 128), 256, GT_SMEM>>>(
        Ph, Pl, Vth, Vtl, nullptr, out, SEQ, MIDD, SEQ);
}

// round 14
// speedup vs baseline: 3.1986x; 1.0002x over previous
#include <cuda_runtime.h>
#include <cuda_bf16.h>
#include <cstdint>

#define SEQ  8192
#define EMB  1024
#define MIDD 1024

// ---------------------------------------------------------------------------
// Scratch (__device__ globals: allocation-free)
// ---------------------------------------------------------------------------
__device__ float g_Q[SEQ * MIDD];
__device__ float g_K[SEQ * MIDD];
__device__ float g_V[SEQ * MIDD];
__device__ float g_S[(size_t)SEQ * (size_t)SEQ];  // fp32 scores (256 MB)

__device__ __nv_bfloat16 g_Xh[SEQ * EMB],  g_Xl[SEQ * EMB];
__device__ __nv_bfloat16 g_Wqh[MIDD * EMB], g_Wql[MIDD * EMB];
__device__ __nv_bfloat16 g_Wkh[MIDD * EMB], g_Wkl[MIDD * EMB];
__device__ __nv_bfloat16 g_Wvh[MIDD * EMB], g_Wvl[MIDD * EMB];
__device__ __nv_bfloat16 g_Qh[SEQ * MIDD], g_Ql[SEQ * MIDD];
__device__ __nv_bfloat16 g_Kh[SEQ * MIDD], g_Kl[SEQ * MIDD];
__device__ __nv_bfloat16 g_Vth[(size_t)MIDD * SEQ], g_Vtl[(size_t)MIDD * SEQ];  // V^T
__device__ __nv_bfloat16 g_Ph[(size_t)SEQ * SEQ], g_Pl[(size_t)SEQ * SEQ];      // weights

// ---------------------------------------------------------------------------
// PTX helpers — compute_103-legal only: cp.async, ldmatrix, mma.sync bf16.
// ---------------------------------------------------------------------------
static __device__ __forceinline__ uint32_t smem_u32(const void* p) {
    uint32_t a;
    asm("{ .reg .u64 t; cvta.to.shared.u64 t, %1; cvt.u32.u64 %0, t; }"
        : "=r"(a) : "l"(p));
    return a;
}

#define CP_ASYNC16(saddr, gptr) \
    asm volatile("cp.async.cg.shared.global [%0], [%1], 16;" \
                 :: "r"(saddr), "l"(gptr))
#define CP_COMMIT() asm volatile("cp.async.commit_group;" ::: "memory")
#define CP_WAIT1()  asm volatile("cp.async.wait_group 1;" ::: "memory")
#define CP_WAIT0()  asm volatile("cp.async.wait_group 0;" ::: "memory")

static __device__ __forceinline__ void ldmx4(uint32_t* r, uint32_t addr) {
    asm volatile("ldmatrix.sync.aligned.m8n8.x4.shared.b16 {%0,%1,%2,%3}, [%4];"
                 : "=r"(r[0]), "=r"(r[1]), "=r"(r[2]), "=r"(r[3]) : "r"(addr));
}

static __device__ __forceinline__ void mma_bf16(float* c, const uint32_t* a,
                                                const uint32_t* b) {
    asm volatile(
        "mma.sync.aligned.m16n8k16.row.col.f32.bf16.bf16.f32 "
        "{%0,%1,%2,%3}, {%4,%5,%6,%7}, {%8,%9}, {%0,%1,%2,%3};"
        : "+f"(c[0]), "+f"(c[1]), "+f"(c[2]), "+f"(c[3])
        : "r"(a[0]), "r"(a[1]), "r"(a[2]), "r"(a[3]), "r"(b[0]), "r"(b[1]));
}

// ---------------------------------------------------------------------------
// Split-bf16 NT GEMM on HMMA: C[M_,N_] = (Ah+Al)(Bh+Bl)^T (+bias), fp32 out.
// Tile 128x128, BK=64, 8 warps (4Mx2N), each 32x64 via m16n8k16 fragments.
// 3 MMA passes per fragment: AhBh + AhBl + AlBh (residual ~ eps_bf16^2).
// 3-stage cp.async pipeline, ONE __syncthreads per k-tile:
//   pre-issue tiles 0,1; iter t: wait_group(1) [tile t ready], barrier,
//   issue tile t+2 (its stage was last read at iter t-1, ordered by barrier),
//   compute tile t.
// ---------------------------------------------------------------------------
#define STAGE   65536     // 4 operand quadrants x 16 KB
#define NSTAGE  3
#define OFF_AH  0
#define OFF_AL  16384
#define OFF_BH  32768
#define OFF_BL  49152
#define GT_SMEM (NSTAGE * STAGE + 1024)

__global__ __launch_bounds__(256, 1)
void gemm_tc(const __nv_bfloat16* __restrict__ Ah, const __nv_bfloat16* __restrict__ Al,
             const __nv_bfloat16* __restrict__ Bh, const __nv_bfloat16* __restrict__ Bl,
             const float* __restrict__ bias, float* __restrict__ C,
             int M_, int N_, int K_)
{
    extern __shared__ char smem_raw[];
    const uint32_t raw = smem_u32(smem_raw);
    const uint32_t SB = (raw + 1023u) & ~1023u;  // 1KB-align buffers

    const int tid = threadIdx.x;
    const int wid = tid >> 5;
    const int lane = tid & 31;
    const int warp_m = wid & 3;   // 0..3 -> 32-row slab
    const int warp_n = wid >> 2;  // 0..1 -> 64-col slab
    const int bm = blockIdx.y * 128;
    const int bn = blockIdx.x * 128;

    // ---- per-thread loader precompute (4x 16B chunks per quadrant) ----
    int l_soff[4];
    size_t l_ga[4], l_gb[4];
#pragma unroll
    for (int i = 0; i < 4; ++i) {
        const int idx = tid + i * 256;   // 0..1023
        const int row = idx >> 3;        // 0..127
        const int ch  = idx & 7;         // 16B chunk in 128B row
        l_soff[i] = row * 128 + ((ch ^ (row & 7)) << 4);
        l_ga[i] = (size_t)(bm + row) * K_ + ch * 8;
        l_gb[i] = (size_t)(bn + row) * K_ + ch * 8;
    }

    auto issue = [&](int t) {
        const uint32_t buf = SB + (t % NSTAGE) * STAGE;
        const size_t kofs = (size_t)t * 64;
#pragma unroll
        for (int i = 0; i < 4; ++i) {
            CP_ASYNC16(buf + OFF_AH + l_soff[i], Ah + l_ga[i] + kofs);
            CP_ASYNC16(buf + OFF_AL + l_soff[i], Al + l_ga[i] + kofs);
            CP_ASYNC16(buf + OFF_BH + l_soff[i], Bh + l_gb[i] + kofs);
            CP_ASYNC16(buf + OFF_BL + l_soff[i], Bl + l_gb[i] + kofs);
        }
        CP_COMMIT();
    };

    // ---- ldmatrix address components ----
    const int a_rit = (lane & 7) + ((lane >> 3) & 1) * 8;  // A row-in-16
    const int a_kq  = lane >> 4;                           // A k-chunk select
    const int b_rit = (lane & 7) + (lane >> 4) * 8;        // B row-in-16
    const int b_kq  = (lane >> 3) & 1;                     // B k-chunk select

    float acc[2][8][4];
#pragma unroll
    for (int mt = 0; mt < 2; ++mt)
#pragma unroll
        for (int n8 = 0; n8 < 8; ++n8)
#pragma unroll
            for (int j = 0; j < 4; ++j) acc[mt][n8][j] = 0.f;

    const int KT = K_ / 64;
    issue(0);
    if (KT > 1) issue(1);

#pragma unroll 1
    for (int t = 0; t < KT; ++t) {
        if (t + 1 < KT) CP_WAIT1(); else CP_WAIT0();
        __syncthreads();  // tile t visible to all; stage (t+2)%3 readers done
        if (t + 2 < KT) issue(t + 2);

        const uint32_t buf = SB + (t % NSTAGE) * STAGE;
#pragma unroll
        for (int s = 0; s < 4; ++s) {
            uint32_t ah[2][4], al[2][4], bh[4][4], bl[4][4];
#pragma unroll
            for (int mt = 0; mt < 2; ++mt) {
                const int row = warp_m * 32 + mt * 16 + a_rit;
                const int ck  = s * 2 + a_kq;
                const uint32_t off = row * 128 + ((ck ^ (row & 7)) << 4);
                ldmx4(ah[mt], buf + OFF_AH + off);
                ldmx4(al[mt], buf + OFF_AL + off);
            }
#pragma unroll
            for (int nt = 0; nt < 4; ++nt) {
                const int row = warp_n * 64 + nt * 16 + b_rit;
                const int ck  = s * 2 + b_kq;
                const uint32_t off = row * 128 + ((ck ^ (row & 7)) << 4);
                ldmx4(bh[nt], buf + OFF_BH + off);
                ldmx4(bl[nt], buf + OFF_BL + off);
            }
            // 3 passes: AhBh + AhBl + AlBh
#pragma unroll
            for (int mt = 0; mt < 2; ++mt)
#pragma unroll
                for (int n8 = 0; n8 < 8; ++n8) {
                    const uint32_t* ph = &bh[n8 >> 1][(n8 & 1) * 2];
                    const uint32_t* pl = &bl[n8 >> 1][(n8 & 1) * 2];
                    mma_bf16(acc[mt][n8], ah[mt], ph);
                    mma_bf16(acc[mt][n8], ah[mt], pl);
                    mma_bf16(acc[mt][n8], al[mt], ph);
                }
        }
        // no trailing barrier: next iteration's top barrier orders stage reuse
    }

    // ---- epilogue: c-fragment -> gmem (coalesced float2), + bias ----
    const int g  = lane >> 2;   // fragment row 0..7
    const int tg = lane & 3;    // col pair 0..3
#pragma unroll
    for (int mt = 0; mt < 2; ++mt) {
        const int row0 = bm + warp_m * 32 + mt * 16 + g;
#pragma unroll
        for (int n8 = 0; n8 < 8; ++n8) {
            const int col = bn + warp_n * 64 + n8 * 8 + tg * 2;
            float2 b2 = make_float2(0.f, 0.f);
            if (bias) b2 = *(const float2*)(bias + col);
            float2 v0 = make_float2(acc[mt][n8][0] + b2.x, acc[mt][n8][1] + b2.y);
            float2 v1 = make_float2(acc[mt][n8][2] + b2.x, acc[mt][n8][3] + b2.y);
            *(float2*)(C + (size_t)row0 * N_ + col)       = v0;
            *(float2*)(C + (size_t)(row0 + 8) * N_ + col) = v1;
        }
    }
}

// ---------------------------------------------------------------------------
// fp32 -> (hi, lo) bf16 split
// ---------------------------------------------------------------------------
static __device__ __forceinline__ void split1(float x, __nv_bfloat16& h, __nv_bfloat16& l) {
    h = __float2bfloat16(x);
    l = __float2bfloat16(x - __bfloat162float(h));
}

__global__ __launch_bounds__(256)
void split_hilo(const float* __restrict__ x, __nv_bfloat16* __restrict__ H,
                __nv_bfloat16* __restrict__ L, int n4)
{
    int i = blockIdx.x * 256 + threadIdx.x;
    if (i >= n4) return;
    float4 v = ((const float4*)x)[i];
    __nv_bfloat16 h0, h1, h2, h3, l0, l1, l2, l3;
    split1(v.x, h0, l0); split1(v.y, h1, l1);
    split1(v.z, h2, l2); split1(v.w, h3, l3);
    ((__nv_bfloat162*)H)[2 * i]     = __halves2bfloat162(h0, h1);
    ((__nv_bfloat162*)H)[2 * i + 1] = __halves2bfloat162(h2, h3);
    ((__nv_bfloat162*)L)[2 * i]     = __halves2bfloat162(l0, l1);
    ((__nv_bfloat162*)L)[2 * i + 1] = __halves2bfloat162(l2, l3);
}

// ---------------------------------------------------------------------------
// Row rsqrt-norm + split to bf16 hi/lo. One block per row (MIDD=1024).
// ---------------------------------------------------------------------------
__global__ __launch_bounds__(256)
void rnorm_hilo(const float* __restrict__ X, __nv_bfloat16* __restrict__ H,
                __nv_bfloat16* __restrict__ L)
{
    const size_t roff = (size_t)blockIdx.x * MIDD;
    const float4* p = (const float4*)(X + roff);
    const int t = threadIdx.x;
    float4 v = p[t];
    float s = v.x * v.x + v.y * v.y + v.z * v.z + v.w * v.w;
#pragma unroll
    for (int o = 16; o > 0; o >>= 1) s += __shfl_xor_sync(0xffffffffu, s, o);
    __shared__ float sh[8];
    if ((t & 31) == 0) sh[t >> 5] = s;
    __syncthreads();
    float tot = 0.f;
#pragma unroll
    for (int i = 0; i < 8; ++i) tot += sh[i];
    const float inv = rsqrtf(tot);
    v.x *= inv; v.y *= inv; v.z *= inv; v.w *= inv;
    __nv_bfloat16 h0, h1, h2, h3, l0, l1, l2, l3;
    split1(v.x, h0, l0); split1(v.y, h1, l1);
    split1(v.z, h2, l2); split1(v.w, h3, l3);
    __nv_bfloat162* H2 = (__nv_bfloat162*)(H + roff);
    __nv_bfloat162* L2 = (__nv_bfloat162*)(L + roff);
    H2[2 * t]     = __halves2bfloat162(h0, h1);
    H2[2 * t + 1] = __halves2bfloat162(h2, h3);
    L2[2 * t]     = __halves2bfloat162(l0, l1);
    L2[2 * t + 1] = __halves2bfloat162(l2, l3);
}

// ---------------------------------------------------------------------------
// V [SEQ, MIDD] fp32 -> V^T hi/lo bf16 [MIDD, SEQ]
// ---------------------------------------------------------------------------
__global__ __launch_bounds__(256)
void transpose_hilo(const float* __restrict__ V, __nv_bfloat16* __restrict__ Th,
                    __nv_bfloat16* __restrict__ Tl)
{
    __shared__ float tile[32][33];
    const int tx = threadIdx.x;
    const int ty = threadIdx.y;
    const int x0 = blockIdx.x * 32;
    const int y0 = blockIdx.y * 32;
#pragma unroll
    for (int j = ty; j < 32; j += 8)
        tile[j][tx] = V[(size_t)(y0 + j) * MIDD + x0 + tx];
    __syncthreads();
#pragma unroll
    for (int j = ty; j < 32; j += 8) {
        float val = tile[tx][j];
        __nv_bfloat16 h, l;
        split1(val, h, l);
        const size_t o = (size_t)(x0 + j) * SEQ + y0 + tx;
        Th[o] = h;
        Tl[o] = l;
    }
}

// ---------------------------------------------------------------------------
// Row softmax over fp32 scores, emits hi/lo bf16 weights. 1024 thr/row.
// ---------------------------------------------------------------------------
__global__ __launch_bounds__(1024)
void softmax_hilo(const float* __restrict__ Sm, __nv_bfloat16* __restrict__ H,
                  __nv_bfloat16* __restrict__ L)
{
    const size_t roff = (size_t)blockIdx.x * SEQ;
    const float4* p = (const float4*)(Sm + roff);
    const int t = threadIdx.x;
    float4 v0 = p[t];
    float4 v1 = p[t + 1024];

    float m = fmaxf(fmaxf(fmaxf(v0.x, v0.y), fmaxf(v0.z, v0.w)),
                    fmaxf(fmaxf(v1.x, v1.y), fmaxf(v1.z, v1.w)));
#pragma unroll
    for (int o = 16; o > 0; o >>= 1) m = fmaxf(m, __shfl_xor_sync(0xffffffffu, m, o));
    __shared__ float sh[32];
    if ((t & 31) == 0) sh[t >> 5] = m;
    __syncthreads();
    float bmax = sh[0];
#pragma unroll
    for (int i = 1; i < 32; ++i) bmax = fmaxf(bmax, sh[i]);

    v0.x = __expf(v0.x - bmax); v0.y = __expf(v0.y - bmax);
    v0.z = __expf(v0.z - bmax); v0.w = __expf(v0.w - bmax);
    v1.x = __expf(v1.x - bmax); v1.y = __expf(v1.y - bmax);
    v1.z = __expf(v1.z - bmax); v1.w = __expf(v1.w - bmax);

    float s = v0.x + v0.y + v0.z + v0.w + v1.x + v1.y + v1.z + v1.w;
#pragma unroll
    for (int o = 16; o > 0; o >>= 1) s += __shfl_xor_sync(0xffffffffu, s, o);
    __syncthreads();
    if ((t & 31) == 0) sh[t >> 5] = s;
    __syncthreads();
    float tot = 0.f;
#pragma unroll
    for (int i = 0; i < 32; ++i) tot += sh[i];
    const float inv = 1.0f / tot;

    v0.x *= inv; v0.y *= inv; v0.z *= inv; v0.w *= inv;
    v1.x *= inv; v1.y *= inv; v1.z *= inv; v1.w *= inv;

    __nv_bfloat162* H2 = (__nv_bfloat162*)(H + roff);
    __nv_bfloat162* L2 = (__nv_bfloat162*)(L + roff);
    __nv_bfloat16 h0, h1, h2, h3, l0, l1, l2, l3;
    split1(v0.x, h0, l0); split1(v0.y, h1, l1);
    split1(v0.z, h2, l2); split1(v0.w, h3, l3);
    H2[2 * t]     = __halves2bfloat162(h0, h1);
    H2[2 * t + 1] = __halves2bfloat162(h2, h3);
    L2[2 * t]     = __halves2bfloat162(l0, l1);
    L2[2 * t + 1] = __halves2bfloat162(l2, l3);
    split1(v1.x, h0, l0); split1(v1.y, h1, l1);
    split1(v1.z, h2, l2); split1(v1.w, h3, l3);
    H2[2048 + 2 * t]     = __halves2bfloat162(h0, h1);
    H2[2048 + 2 * t + 1] = __halves2bfloat162(h2, h3);
    L2[2048 + 2 * t]     = __halves2bfloat162(l0, l1);
    L2[2048 + 2 * t + 1] = __halves2bfloat162(l2, l3);
}

// ---------------------------------------------------------------------------
// Orchestration (graph-capturable: launches only)
// ---------------------------------------------------------------------------
extern "C" void kernel_launch(void* const* d_in, const int* in_sizes, int n_in,
                              void* d_out, int out_size)
{
    const float* X  = (const float*)d_in[0];
    const float* Wq = (const float*)d_in[1];
    const float* bq = (const float*)d_in[2];
    const float* Wk = (const float*)d_in[3];
    const float* bk = (const float*)d_in[4];
    const float* Wv = (const float*)d_in[5];
    const float* bv = (const float*)d_in[6];
    float* out = (float*)d_out;

    float *Qf, *Kf, *Vf, *Sc;
    __nv_bfloat16 *Xh, *Xl, *Wqh, *Wql, *Wkh, *Wkl, *Wvh, *Wvl;
    __nv_bfloat16 *Qh, *Ql, *Kh, *Kl, *Vth, *Vtl, *Ph, *Pl;
    cudaGetSymbolAddress((void**)&Qf, g_Q);
    cudaGetSymbolAddress((void**)&Kf, g_K);
    cudaGetSymbolAddress((void**)&Vf, g_V);
    cudaGetSymbolAddress((void**)&Sc, g_S);
    cudaGetSymbolAddress((void**)&Xh, g_Xh);   cudaGetSymbolAddress((void**)&Xl, g_Xl);
    cudaGetSymbolAddress((void**)&Wqh, g_Wqh); cudaGetSymbolAddress((void**)&Wql, g_Wql);
    cudaGetSymbolAddress((void**)&Wkh, g_Wkh); cudaGetSymbolAddress((void**)&Wkl, g_Wkl);
    cudaGetSymbolAddress((void**)&Wvh, g_Wvh); cudaGetSymbolAddress((void**)&Wvl, g_Wvl);
    cudaGetSymbolAddress((void**)&Qh, g_Qh);   cudaGetSymbolAddress((void**)&Ql, g_Ql);
    cudaGetSymbolAddress((void**)&Kh, g_Kh);   cudaGetSymbolAddress((void**)&Kl, g_Kl);
    cudaGetSymbolAddress((void**)&Vth, g_Vth); cudaGetSymbolAddress((void**)&Vtl, g_Vtl);
    cudaGetSymbolAddress((void**)&Ph, g_Ph);   cudaGetSymbolAddress((void**)&Pl, g_Pl);

    cudaFuncSetAttribute(gemm_tc, cudaFuncAttributeMaxDynamicSharedMemorySize, GT_SMEM);

    // split inputs to bf16 hi/lo
    split_hilo<<<SEQ * EMB / 4 / 256, 256>>>(X, Xh, Xl, SEQ * EMB / 4);
    split_hilo<<<MIDD * EMB / 4 / 256, 256>>>(Wq, Wqh, Wql, MIDD * EMB / 4);
    split_hilo<<<MIDD * EMB / 4 / 256, 256>>>(Wk, Wkh, Wkl, MIDD * EMB / 4);
    split_hilo<<<MIDD * EMB / 4 / 256, 256>>>(Wv, Wvh, Wvl, MIDD * EMB / 4);

    // Q/K/V = X @ W^T + b
    dim3 gQKV(MIDD / 128, SEQ / 128);
    gemm_tc<<<gQKV, 256, GT_SMEM>>>(Xh, Xl, Wqh, Wql, bq, Qf, SEQ, MIDD, EMB);
    gemm_tc<<<gQKV, 256, GT_SMEM>>>(Xh, Xl, Wkh, Wkl, bk, Kf, SEQ, MIDD, EMB);
    gemm_tc<<<gQKV, 256, GT_SMEM>>>(Xh, Xl, Wvh, Wvl, bv, Vf, SEQ, MIDD, EMB);

    // cosine norms folded into operands; V transposed for NT form
    rnorm_hilo<<<SEQ, 256>>>(Qf, Qh, Ql);
    rnorm_hilo<<<SEQ, 256>>>(Kf, Kh, Kl);
    transpose_hilo<<<dim3(MIDD / 32, SEQ / 32), dim3(32, 8)>>>(Vf, Vth, Vtl);

    // scores = Qn @ Kn^T
    gemm_tc<<<dim3(SEQ / 128, SEQ / 128), 256, GT_SMEM>>>(
        Qh, Ql, Kh, Kl, nullptr, Sc, SEQ, SEQ, MIDD);

    // softmax -> bf16 hi/lo weights
    softmax_hilo<<<SEQ, 1024>>>(Sc, Ph, Pl);

    // out = weights @ V = weights @ (V^T)^T
    gemm_tc<<<dim3(MIDD / 128, SEQ / 128), 256, GT_SMEM>>>(
        Ph, Pl, Vth, Vtl, nullptr, out, SEQ, MIDD, SEQ);
}

// round 16
// speedup vs baseline: 3.8515x; 1.2041x over previous
#include <cuda_runtime.h>
#include <cuda_bf16.h>
#include <cstdint>

#define SEQ  8192
#define EMB  1024
#define MIDD 1024

// ---------------------------------------------------------------------------
// Scratch (__device__ globals: allocation-free)
// ---------------------------------------------------------------------------
__device__ float g_Q[SEQ * MIDD];
__device__ float g_K[SEQ * MIDD];
__device__ float g_V[SEQ * MIDD];
__device__ float g_Vt[(size_t)MIDD * SEQ];        // V^T fp32 (tf32-rounded)
__device__ float g_S[(size_t)SEQ * (size_t)SEQ];  // scores -> softmax weights

__device__ __nv_bfloat16 g_Xh[SEQ * EMB],  g_Xl[SEQ * EMB];
__device__ __nv_bfloat16 g_Wqh[MIDD * EMB], g_Wql[MIDD * EMB];
__device__ __nv_bfloat16 g_Wkh[MIDD * EMB], g_Wkl[MIDD * EMB];
__device__ __nv_bfloat16 g_Wvh[MIDD * EMB], g_Wvl[MIDD * EMB];

// ---------------------------------------------------------------------------
// PTX helpers — compute_103-legal only.
// ---------------------------------------------------------------------------
static __device__ __forceinline__ uint32_t smem_u32(const void* p) {
    uint32_t a;
    asm("{ .reg .u64 t; cvta.to.shared.u64 t, %1; cvt.u32.u64 %0, t; }"
        : "=r"(a) : "l"(p));
    return a;
}

#define CP_ASYNC16(saddr, gptr) \
    asm volatile("cp.async.cg.shared.global [%0], [%1], 16;" \
                 :: "r"(saddr), "l"(gptr))
#define CP_COMMIT() asm volatile("cp.async.commit_group;" ::: "memory")
#define CP_WAIT1()  asm volatile("cp.async.wait_group 1;" ::: "memory")
#define CP_WAIT0()  asm volatile("cp.async.wait_group 0;" ::: "memory")

static __device__ __forceinline__ void ldmx4(uint32_t* r, uint32_t addr) {
    asm volatile("ldmatrix.sync.aligned.m8n8.x4.shared.b16 {%0,%1,%2,%3}, [%4];"
                 : "=r"(r[0]), "=r"(r[1]), "=r"(r[2]), "=r"(r[3]) : "r"(addr));
}

static __device__ __forceinline__ void mma_bf16(float* c, const uint32_t* a,
                                                const uint32_t* b) {
    asm volatile(
        "mma.sync.aligned.m16n8k16.row.col.f32.bf16.bf16.f32 "
        "{%0,%1,%2,%3}, {%4,%5,%6,%7}, {%8,%9}, {%0,%1,%2,%3};"
        : "+f"(c[0]), "+f"(c[1]), "+f"(c[2]), "+f"(c[3])
        : "r"(a[0]), "r"(a[1]), "r"(a[2]), "r"(a[3]), "r"(b[0]), "r"(b[1]));
}

static __device__ __forceinline__ void mma_tf32(float* c, const uint32_t* a,
                                                const uint32_t* b) {
    asm volatile(
        "mma.sync.aligned.m16n8k8.row.col.f32.tf32.tf32.f32 "
        "{%0,%1,%2,%3}, {%4,%5,%6,%7}, {%8,%9}, {%0,%1,%2,%3};"
        : "+f"(c[0]), "+f"(c[1]), "+f"(c[2]), "+f"(c[3])
        : "r"(a[0]), "r"(a[1]), "r"(a[2]), "r"(a[3]), "r"(b[0]), "r"(b[1]));
}

static __device__ __forceinline__ float rtf32(float x) {
    uint32_t r;
    asm("cvt.rna.tf32.f32 %0, %1;" : "=r"(r) : "f"(x));
    return __uint_as_float(r);
}

// ===========================================================================
// KERNEL 1: split-bf16 NT GEMM on HMMA (QKV projections; exact to ~eps^2).
// Unchanged from the passing R13/R14 kernel. Tile 128x128, BK=64, 3 stages.
// ===========================================================================
#define STAGE   65536
#define NSTAGE  3
#define OFF_AH  0
#define OFF_AL  16384
#define OFF_BH  32768
#define OFF_BL  49152
#define GT_SMEM (NSTAGE * STAGE + 1024)

__global__ __launch_bounds__(256, 1)
void gemm_tc(const __nv_bfloat16* __restrict__ Ah, const __nv_bfloat16* __restrict__ Al,
             const __nv_bfloat16* __restrict__ Bh, const __nv_bfloat16* __restrict__ Bl,
             const float* __restrict__ bias, float* __restrict__ C,
             int M_, int N_, int K_)
{
    extern __shared__ char smem_raw[];
    const uint32_t raw = smem_u32(smem_raw);
    const uint32_t SB = (raw + 1023u) & ~1023u;

    const int tid = threadIdx.x;
    const int wid = tid >> 5;
    const int lane = tid & 31;
    const int warp_m = wid & 3;
    const int warp_n = wid >> 2;
    const int bm = blockIdx.y * 128;
    const int bn = blockIdx.x * 128;

    int l_soff[4];
    size_t l_ga[4], l_gb[4];
#pragma unroll
    for (int i = 0; i < 4; ++i) {
        const int idx = tid + i * 256;
        const int row = idx >> 3;
        const int ch  = idx & 7;
        l_soff[i] = row * 128 + ((ch ^ (row & 7)) << 4);
        l_ga[i] = (size_t)(bm + row) * K_ + ch * 8;
        l_gb[i] = (size_t)(bn + row) * K_ + ch * 8;
    }

    auto issue = [&](int t) {
        const uint32_t buf = SB + (t % NSTAGE) * STAGE;
        const size_t kofs = (size_t)t * 64;
#pragma unroll
        for (int i = 0; i < 4; ++i) {
            CP_ASYNC16(buf + OFF_AH + l_soff[i], Ah + l_ga[i] + kofs);
            CP_ASYNC16(buf + OFF_AL + l_soff[i], Al + l_ga[i] + kofs);
            CP_ASYNC16(buf + OFF_BH + l_soff[i], Bh + l_gb[i] + kofs);
            CP_ASYNC16(buf + OFF_BL + l_soff[i], Bl + l_gb[i] + kofs);
        }
        CP_COMMIT();
    };

    const int a_rit = (lane & 7) + ((lane >> 3) & 1) * 8;
    const int a_kq  = lane >> 4;
    const int b_rit = (lane & 7) + (lane >> 4) * 8;
    const int b_kq  = (lane >> 3) & 1;

    float acc[2][8][4];
#pragma unroll
    for (int mt = 0; mt < 2; ++mt)
#pragma unroll
        for (int n8 = 0; n8 < 8; ++n8)
#pragma unroll
            for (int j = 0; j < 4; ++j) acc[mt][n8][j] = 0.f;

    const int KT = K_ / 64;
    issue(0);
    if (KT > 1) issue(1);

#pragma unroll 1
    for (int t = 0; t < KT; ++t) {
        if (t + 1 < KT) CP_WAIT1(); else CP_WAIT0();
        __syncthreads();
        if (t + 2 < KT) issue(t + 2);

        const uint32_t buf = SB + (t % NSTAGE) * STAGE;
#pragma unroll
        for (int s = 0; s < 4; ++s) {
            uint32_t ah[2][4], al[2][4], bh[4][4], bl[4][4];
#pragma unroll
            for (int mt = 0; mt < 2; ++mt) {
                const int row = warp_m * 32 + mt * 16 + a_rit;
                const int ck  = s * 2 + a_kq;
                const uint32_t off = row * 128 + ((ck ^ (row & 7)) << 4);
                ldmx4(ah[mt], buf + OFF_AH + off);
                ldmx4(al[mt], buf + OFF_AL + off);
            }
#pragma unroll
            for (int nt = 0; nt < 4; ++nt) {
                const int row = warp_n * 64 + nt * 16 + b_rit;
                const int ck  = s * 2 + b_kq;
                const uint32_t off = row * 128 + ((ck ^ (row & 7)) << 4);
                ldmx4(bh[nt], buf + OFF_BH + off);
                ldmx4(bl[nt], buf + OFF_BL + off);
            }
#pragma unroll
            for (int mt = 0; mt < 2; ++mt)
#pragma unroll
                for (int n8 = 0; n8 < 8; ++n8) {
                    const uint32_t* ph = &bh[n8 >> 1][(n8 & 1) * 2];
                    const uint32_t* pl = &bl[n8 >> 1][(n8 & 1) * 2];
                    mma_bf16(acc[mt][n8], ah[mt], ph);
                    mma_bf16(acc[mt][n8], ah[mt], pl);
                    mma_bf16(acc[mt][n8], al[mt], ph);
                }
        }
    }

    const int g  = lane >> 2;
    const int tg = lane & 3;
#pragma unroll
    for (int mt = 0; mt < 2; ++mt) {
        const int row0 = bm + warp_m * 32 + mt * 16 + g;
#pragma unroll
        for (int n8 = 0; n8 < 8; ++n8) {
            const int col = bn + warp_n * 64 + n8 * 8 + tg * 2;
            float2 b2 = make_float2(0.f, 0.f);
            if (bias) b2 = *(const float2*)(bias + col);
            float2 v0 = make_float2(acc[mt][n8][0] + b2.x, acc[mt][n8][1] + b2.y);
            float2 v1 = make_float2(acc[mt][n8][2] + b2.x, acc[mt][n8][3] + b2.y);
            *(float2*)(C + (size_t)row0 * N_ + col)       = v0;
            *(float2*)(C + (size_t)(row0 + 8) * N_ + col) = v1;
        }
    }
}

// ===========================================================================
// KERNEL 2: tf32 single-pass NT GEMM (scores and out; operands pre-rounded).
// C[M_,N_] = A[M_,K_] * B[N_,K_]^T, fp32. CTA tile 256x128, BK=64.
// 8 warps (4M x 2N), warp 64x64 via m16n8k8 tf32 fragments (128 acc regs).
// fp32 smem, 4B-XOR swizzle (col ^ (row&7)<<2): conflict-free scalar LDS +
// 16B cp.async stores. 2-stage pipeline (throughput-bound; depth irrelevant).
// ===========================================================================
#define T_ASTG 65536                 // 256 rows x 64 f32
#define T_BSTG 32768                 // 128 rows x 64 f32
#define T_STG  (T_ASTG + T_BSTG)     // 98304
#define T_SMEM (2 * T_STG + 1024)    // 197632 <= 227KB

__global__ __launch_bounds__(256, 1)
void gemm_tf(const float* __restrict__ A, const float* __restrict__ B,
             float* __restrict__ C, int M_, int N_, int K_)
{
    extern __shared__ char smem_raw[];
    const uint32_t raw = smem_u32(smem_raw);
    const uint32_t SB = (raw + 1023u) & ~1023u;
    char* smem = smem_raw + (SB - raw);

    const int tid = threadIdx.x;
    const int wid = tid >> 5;
    const int lane = tid & 31;
    const int warp_m = wid & 3;   // 0..3 -> 64-row slab
    const int warp_n = wid >> 2;  // 0..1 -> 64-col slab
    const int bm = blockIdx.y * 256;
    const int bn = blockIdx.x * 128;

    auto issue = [&](int t) {
        const uint32_t bufA = SB + (t & 1) * T_STG;
        const uint32_t bufB = bufA + T_ASTG;
        const size_t kofs = (size_t)t * 64;
#pragma unroll
        for (int i = 0; i < 16; ++i) {          // A: 4096 chunks / 256 thr
            const int idx = tid + i * 256;
            const int row = idx >> 4, ch = idx & 15;
            const uint32_t soff = row * 256 + ((ch ^ (row & 7)) << 4);
            CP_ASYNC16(bufA + soff, A + (size_t)(bm + row) * K_ + kofs + ch * 4);
        }
#pragma unroll
        for (int i = 0; i < 8; ++i) {           // B: 2048 chunks
            const int idx = tid + i * 256;
            const int row = idx >> 4, ch = idx & 15;
            const uint32_t soff = row * 256 + ((ch ^ (row & 7)) << 4);
            CP_ASYNC16(bufB + soff, B + (size_t)(bn + row) * K_ + kofs + ch * 4);
        }
        CP_COMMIT();
    };

    const int g  = lane >> 2;   // 0..7
    const int tg = lane & 3;    // 0..3
    const int sw = g << 2;      // xor term: rows r and r+8 share (r&7)=g

    float acc[4][8][4];
#pragma unroll
    for (int mt = 0; mt < 4; ++mt)
#pragma unroll
        for (int j = 0; j < 8; ++j)
#pragma unroll
            for (int q = 0; q < 4; ++q) acc[mt][j][q] = 0.f;

    const int KT = K_ / 64;
    issue(0);
    if (KT > 1) issue(1);

#pragma unroll 1
    for (int t = 0; t < KT; ++t) {
        if (t + 1 < KT) CP_WAIT1(); else CP_WAIT0();
        __syncthreads();

        const char* bufA = smem + (t & 1) * T_STG;
        const char* bufB = bufA + T_ASTG;
#pragma unroll
        for (int s = 0; s < 8; ++s) {
            const int c0 = s * 8 + tg;
            const uint32_t p0 = (uint32_t)((c0 ^ sw) << 2);        // byte off of col c0
            const uint32_t p1 = (uint32_t)(((c0 + 4) ^ sw) << 2);  // col c0+4
            uint32_t af[4][4], bf[8][2];
#pragma unroll
            for (int mt = 0; mt < 4; ++mt) {
                const int r0 = warp_m * 64 + mt * 16 + g;
                const char* base0 = bufA + r0 * 256;
                af[mt][0] = *(const uint32_t*)(base0 + p0);
                af[mt][1] = *(const uint32_t*)(base0 + 2048 + p0);  // row+8
                af[mt][2] = *(const uint32_t*)(base0 + p1);
                af[mt][3] = *(const uint32_t*)(base0 + 2048 + p1);
            }
#pragma unroll
            for (int j = 0; j < 8; ++j) {
                const int rn = warp_n * 64 + j * 8 + g;
                const char* basen = bufB + rn * 256;
                bf[j][0] = *(const uint32_t*)(basen + p0);
                bf[j][1] = *(const uint32_t*)(basen + p1);
            }
#pragma unroll
            for (int mt = 0; mt < 4; ++mt)
#pragma unroll
                for (int j = 0; j < 8; ++j)
                    mma_tf32(acc[mt][j], af[mt], bf[j]);
        }
        __syncthreads();
        if (t + 2 < KT) issue(t + 2);
    }

    // epilogue: fragments -> coalesced float2 stores
#pragma unroll
    for (int mt = 0; mt < 4; ++mt) {
        const int row0 = bm + warp_m * 64 + mt * 16 + g;
#pragma unroll
        for (int j = 0; j < 8; ++j) {
            const int col = bn + warp_n * 64 + j * 8 + tg * 2;
            *(float2*)(C + (size_t)row0 * N_ + col) =
                make_float2(acc[mt][j][0], acc[mt][j][1]);
            *(float2*)(C + (size_t)(row0 + 8) * N_ + col) =
                make_float2(acc[mt][j][2], acc[mt][j][3]);
        }
    }
}

// ---------------------------------------------------------------------------
// fp32 -> (hi, lo) bf16 split (for QKV operands)
// ---------------------------------------------------------------------------
static __device__ __forceinline__ void split1(float x, __nv_bfloat16& h, __nv_bfloat16& l) {
    h = __float2bfloat16(x);
    l = __float2bfloat16(x - __bfloat162float(h));
}

__global__ __launch_bounds__(256)
void split_hilo(const float* __restrict__ x, __nv_bfloat16* __restrict__ H,
                __nv_bfloat16* __restrict__ L, int n4)
{
    int i = blockIdx.x * 256 + threadIdx.x;
    if (i >= n4) return;
    float4 v = ((const float4*)x)[i];
    __nv_bfloat16 h0, h1, h2, h3, l0, l1, l2, l3;
    split1(v.x, h0, l0); split1(v.y, h1, l1);
    split1(v.z, h2, l2); split1(v.w, h3, l3);
    ((__nv_bfloat162*)H)[2 * i]     = __halves2bfloat162(h0, h1);
    ((__nv_bfloat162*)H)[2 * i + 1] = __halves2bfloat162(h2, h3);
    ((__nv_bfloat162*)L)[2 * i]     = __halves2bfloat162(l0, l1);
    ((__nv_bfloat162*)L)[2 * i + 1] = __halves2bfloat162(l2, l3);
}

// ---------------------------------------------------------------------------
// Row rsqrt-norm, tf32-rounded, in place. One block per row (MIDD=1024).
// ---------------------------------------------------------------------------
__global__ __launch_bounds__(256)
void rnorm_tf(float* __restrict__ X)
{
    float4* p = (float4*)(X + (size_t)blockIdx.x * MIDD);
    const int t = threadIdx.x;
    float4 v = p[t];
    float s = v.x * v.x + v.y * v.y + v.z * v.z + v.w * v.w;
#pragma unroll
    for (int o = 16; o > 0; o >>= 1) s += __shfl_xor_sync(0xffffffffu, s, o);
    __shared__ float sh[8];
    if ((t & 31) == 0) sh[t >> 5] = s;
    __syncthreads();
    float tot = 0.f;
#pragma unroll
    for (int i = 0; i < 8; ++i) tot += sh[i];
    const float inv = rsqrtf(tot);
    v.x = rtf32(v.x * inv); v.y = rtf32(v.y * inv);
    v.z = rtf32(v.z * inv); v.w = rtf32(v.w * inv);
    p[t] = v;
}

// ---------------------------------------------------------------------------
// V [SEQ, MIDD] fp32 -> V^T fp32 tf32-rounded [MIDD, SEQ]
// ---------------------------------------------------------------------------
__global__ __launch_bounds__(256)
void transpose_tf(const float* __restrict__ V, float* __restrict__ T_)
{
    __shared__ float tile[32][33];
    const int tx = threadIdx.x;
    const int ty = threadIdx.y;
    const int x0 = blockIdx.x * 32;
    const int y0 = blockIdx.y * 32;
#pragma unroll
    for (int j = ty; j < 32; j += 8)
        tile[j][tx] = V[(size_t)(y0 + j) * MIDD + x0 + tx];
    __syncthreads();
#pragma unroll
    for (int j = ty; j < 32; j += 8)
        T_[(size_t)(x0 + j) * SEQ + y0 + tx] = rtf32(tile[tx][j]);
}

// ---------------------------------------------------------------------------
// Row softmax, tf32-rounded output, in place. 1024 thr/row over 8192 cols.
// ---------------------------------------------------------------------------
__global__ __launch_bounds__(1024)
void softmax_tf(float* __restrict__ Sm)
{
    float4* p = (float4*)(Sm + (size_t)blockIdx.x * SEQ);
    const int t = threadIdx.x;
    float4 v0 = p[t];
    float4 v1 = p[t + 1024];

    float m = fmaxf(fmaxf(fmaxf(v0.x, v0.y), fmaxf(v0.z, v0.w)),
                    fmaxf(fmaxf(v1.x, v1.y), fmaxf(v1.z, v1.w)));
#pragma unroll
    for (int o = 16; o > 0; o >>= 1) m = fmaxf(m, __shfl_xor_sync(0xffffffffu, m, o));
    __shared__ float sh[32];
    if ((t & 31) == 0) sh[t >> 5] = m;
    __syncthreads();
    float bmax = sh[0];
#pragma unroll
    for (int i = 1; i < 32; ++i) bmax = fmaxf(bmax, sh[i]);

    v0.x = __expf(v0.x - bmax); v0.y = __expf(v0.y - bmax);
    v0.z = __expf(v0.z - bmax); v0.w = __expf(v0.w - bmax);
    v1.x = __expf(v1.x - bmax); v1.y = __expf(v1.y - bmax);
    v1.z = __expf(v1.z - bmax); v1.w = __expf(v1.w - bmax);

    float s = v0.x + v0.y + v0.z + v0.w + v1.x + v1.y + v1.z + v1.w;
#pragma unroll
    for (int o = 16; o > 0; o >>= 1) s += __shfl_xor_sync(0xffffffffu, s, o);
    __syncthreads();
    if ((t & 31) == 0) sh[t >> 5] = s;
    __syncthreads();
    float tot = 0.f;
#pragma unroll
    for (int i = 0; i < 32; ++i) tot += sh[i];
    const float inv = 1.0f / tot;

    v0.x = rtf32(v0.x * inv); v0.y = rtf32(v0.y * inv);
    v0.z = rtf32(v0.z * inv); v0.w = rtf32(v0.w * inv);
    v1.x = rtf32(v1.x * inv); v1.y = rtf32(v1.y * inv);
    v1.z = rtf32(v1.z * inv); v1.w = rtf32(v1.w * inv);
    p[t] = v0;
    p[t + 1024] = v1;
}

// ---------------------------------------------------------------------------
// Orchestration (graph-capturable: launches only)
// ---------------------------------------------------------------------------
extern "C" void kernel_launch(void* const* d_in, const int* in_sizes, int n_in,
                              void* d_out, int out_size)
{
    const float* X  = (const float*)d_in[0];
    const float* Wq = (const float*)d_in[1];
    const float* bq = (const float*)d_in[2];
    const float* Wk = (const float*)d_in[3];
    const float* bk = (const float*)d_in[4];
    const float* Wv = (const float*)d_in[5];
    const float* bv = (const float*)d_in[6];
    float* out = (float*)d_out;

    float *Qf, *Kf, *Vf, *Vt, *Sc;
    __nv_bfloat16 *Xh, *Xl, *Wqh, *Wql, *Wkh, *Wkl, *Wvh, *Wvl;
    cudaGetSymbolAddress((void**)&Qf, g_Q);
    cudaGetSymbolAddress((void**)&Kf, g_K);
    cudaGetSymbolAddress((void**)&Vf, g_V);
    cudaGetSymbolAddress((void**)&Vt, g_Vt);
    cudaGetSymbolAddress((void**)&Sc, g_S);
    cudaGetSymbolAddress((void**)&Xh, g_Xh);   cudaGetSymbolAddress((void**)&Xl, g_Xl);
    cudaGetSymbolAddress((void**)&Wqh, g_Wqh); cudaGetSymbolAddress((void**)&Wql, g_Wql);
    cudaGetSymbolAddress((void**)&Wkh, g_Wkh); cudaGetSymbolAddress((void**)&Wkl, g_Wkl);
    cudaGetSymbolAddress((void**)&Wvh, g_Wvh); cudaGetSymbolAddress((void**)&Wvl, g_Wvl);

    cudaFuncSetAttribute(gemm_tc, cudaFuncAttributeMaxDynamicSharedMemorySize, GT_SMEM);
    cudaFuncSetAttribute(gemm_tf, cudaFuncAttributeMaxDynamicSharedMemorySize, T_SMEM);

    // split inputs to bf16 hi/lo (QKV path)
    split_hilo<<<SEQ * EMB / 4 / 256, 256>>>(X, Xh, Xl, SEQ * EMB / 4);
    split_hilo<<<MIDD * EMB / 4 / 256, 256>>>(Wq, Wqh, Wql, MIDD * EMB / 4);
    split_hilo<<<MIDD * EMB / 4 / 256, 256>>>(Wk, Wkh, Wkl, MIDD * EMB / 4);
    split_hilo<<<MIDD * EMB / 4 / 256, 256>>>(Wv, Wvh, Wvl, MIDD * EMB / 4);

    // Q/K/V = X @ W^T + b   (split-bf16 3-pass: near-exact)
    dim3 gQKV(MIDD / 128, SEQ / 128);
    gemm_tc<<<gQKV, 256, GT_SMEM>>>(Xh, Xl, Wqh, Wql, bq, Qf, SEQ, MIDD, EMB);
    gemm_tc<<<gQKV, 256, GT_SMEM>>>(Xh, Xl, Wkh, Wkl, bk, Kf, SEQ, MIDD, EMB);
    gemm_tc<<<gQKV, 256, GT_SMEM>>>(Xh, Xl, Wvh, Wvl, bv, Vf, SEQ, MIDD, EMB);

    // cosine norms folded into operands (tf32-rounded, in place); V^T rounded
    rnorm_tf<<<SEQ, 256>>>(Qf);
    rnorm_tf<<<SEQ, 256>>>(Kf);
    transpose_tf<<<dim3(MIDD / 32, SEQ / 32), dim3(32, 8)>>>(Vf, Vt);

    // scores = Qn @ Kn^T   (tf32 single-pass)
    gemm_tf<<<dim3(SEQ / 128, SEQ / 256), 256, T_SMEM>>>(Qf, Kf, Sc, SEQ, SEQ, MIDD);

    // softmax -> tf32-rounded weights (in place)
    softmax_tf<<<SEQ, 1024>>>(Sc);

    // out = weights @ V = weights @ (V^T)^T   (tf32 single-pass)
    gemm_tf<<<dim3(MIDD / 128, SEQ / 256), 256, T_SMEM>>>(Sc, Vt, out, SEQ, MIDD, SEQ);
}